// round 1
// baseline (speedup 1.0000x reference)
#include <cuda_runtime.h>
#include <math.h>

#define NN 50000       // nodes
#define KD 512         // input feature dim
#define FO 256         // output classes
#define ER 850000      // edges: 800000 random + 50000 self loops

// -------- scratch (device globals; no allocation allowed) --------
__device__ __align__(16) float g_h [(size_t)NN * FO];   // h = x@W          (51.2 MB)
__device__ __align__(16) float g_hp[(size_t)NN * FO];   // segment-sum acc  (51.2 MB)
__device__ float g_srow[NN];
__device__ float g_scol[NN];
__device__ float g_rowsum[NN];
__device__ float g_e[ER];

// ================= K1: SGEMM h = x @ W, also zero g_hp =================
#define BM 128
#define BN 64
#define BK 16
#define TM 8
#define TN 4

__global__ __launch_bounds__(256) void gemm_kernel(const float* __restrict__ x,
                                                   const float* __restrict__ W) {
    __shared__ float As[BM][BK + 4];   // +4 keeps float4 stores 16B-aligned, kills bank conflicts
    __shared__ float Bs[BK][BN];

    int tid = threadIdx.x;
    int tx = tid & 15;        // 0..15 -> N direction (4 cols each)
    int ty = tid >> 4;        // 0..15 -> M direction (8 rows each)
    int m0 = blockIdx.x * BM;
    int n0 = blockIdx.y * BN;

    float acc[TM][TN];
#pragma unroll
    for (int i = 0; i < TM; i++)
#pragma unroll
        for (int j = 0; j < TN; j++) acc[i][j] = 0.f;

    for (int k0 = 0; k0 < KD; k0 += BK) {
        // load A tile: 128x16 = 512 float4, 2 per thread
#pragma unroll
        for (int it = 0; it < 2; it++) {
            int f   = tid + it * 256;
            int row = f >> 2;       // 0..127
            int c4  = f & 3;        // 0..3
            int gr  = m0 + row;
            float4 v = make_float4(0.f, 0.f, 0.f, 0.f);
            if (gr < NN)
                v = *(const float4*)&x[(size_t)gr * KD + k0 + c4 * 4];
            *(float4*)&As[row][c4 * 4] = v;
        }
        // load B tile: 16x64 = 256 float4, 1 per thread
        {
            int row = tid >> 4;     // 0..15 (k)
            int c4  = tid & 15;     // 0..15
            *(float4*)&Bs[row][c4 * 4] =
                *(const float4*)&W[(size_t)(k0 + row) * FO + n0 + c4 * 4];
        }
        __syncthreads();

#pragma unroll
        for (int kk = 0; kk < BK; kk++) {
            float a_[TM];
#pragma unroll
            for (int i = 0; i < TM; i++) a_[i] = As[ty * TM + i][kk];
            float4 b4 = *(float4*)&Bs[kk][tx * TN];
            float b_[TN] = {b4.x, b4.y, b4.z, b4.w};
#pragma unroll
            for (int i = 0; i < TM; i++)
#pragma unroll
                for (int j = 0; j < TN; j++)
                    acc[i][j] = fmaf(a_[i], b_[j], acc[i][j]);
        }
        __syncthreads();
    }

#pragma unroll
    for (int i = 0; i < TM; i++) {
        int gr = m0 + ty * TM + i;
        if (gr < NN) {
            size_t off = (size_t)gr * FO + n0 + tx * TN;
            *(float4*)&g_h [off] = make_float4(acc[i][0], acc[i][1], acc[i][2], acc[i][3]);
            *(float4*)&g_hp[off] = make_float4(0.f, 0.f, 0.f, 0.f);   // zero accumulator
        }
    }
}

// ============ K2: per-node attention scores + rowsum init ============
__global__ __launch_bounds__(256) void scores_kernel(const float* __restrict__ a) {
    int n    = blockIdx.x * (blockDim.x >> 5) + (threadIdx.x >> 5);
    int lane = threadIdx.x & 31;
    if (n >= NN) return;
    const float4* h4  = (const float4*)&g_h[(size_t)n * FO];
    const float4* a14 = (const float4*)a;          // a[0:256]
    const float4* a24 = (const float4*)(a + FO);   // a[256:512]
    float s1 = 0.f, s2 = 0.f;
#pragma unroll
    for (int it = 0; it < 2; it++) {
        int idx = lane + it * 32;                  // 64 float4 per row
        float4 hv = h4[idx];
        float4 va = a14[idx];
        float4 vb = a24[idx];
        s1 += hv.x * va.x + hv.y * va.y + hv.z * va.z + hv.w * va.w;
        s2 += hv.x * vb.x + hv.y * vb.y + hv.z * vb.z + hv.w * vb.w;
    }
#pragma unroll
    for (int off = 16; off; off >>= 1) {
        s1 += __shfl_xor_sync(0xFFFFFFFFu, s1, off);
        s2 += __shfl_xor_sync(0xFFFFFFFFu, s2, off);
    }
    if (lane == 0) {
        g_srow[n]   = s1;
        g_scol[n]   = s2;
        g_rowsum[n] = 0.f;
    }
}

// ============ K3: per-edge coefficient + rowsum accumulation ============
__global__ __launch_bounds__(256) void edge_kernel(const int* __restrict__ row,
                                                   const int* __restrict__ col) {
    int i = blockIdx.x * blockDim.x + threadIdx.x;
    if (i >= ER) return;
    int r = row[i], c = col[i];
    float z = g_srow[r] + g_scol[c];
    float l = z > 0.f ? z : 0.2f * z;        // leaky_relu, slope 0.2
    float e = expf(-l);
    g_e[i] = e;
    atomicAdd(&g_rowsum[r], e);
}

// ============ K4: scatter SpMM: h_prime[row] += e * h[col] ============
// 64 threads per edge, float4 per thread (256 feats), vector reduction atomics.
__global__ __launch_bounds__(256) void scatter_kernel(const int* __restrict__ row,
                                                      const int* __restrict__ col) {
    long long gt = (long long)blockIdx.x * 256 + threadIdx.x;
    int edge = (int)(gt >> 6);
    if (edge >= ER) return;
    int lane = (int)(gt & 63);
    int r = row[edge], c = col[edge];
    float e = g_e[edge];
    float4 hv = *(const float4*)&g_h[(size_t)c * FO + lane * 4];
    float4 m  = make_float4(e * hv.x, e * hv.y, e * hv.z, e * hv.w);
    float* dst = &g_hp[(size_t)r * FO + lane * 4];
    asm volatile("red.global.add.v4.f32 [%0], {%1,%2,%3,%4};"
                 :: "l"(dst), "f"(m.x), "f"(m.y), "f"(m.z), "f"(m.w)
                 : "memory");
}

// ============ K5: normalize + ELU + log_softmax ============
__global__ __launch_bounds__(256) void final_kernel(float* __restrict__ out) {
    int n = blockIdx.x;
    int t = threadIdx.x;
    __shared__ float red[256];

    float rs = g_rowsum[n];
    float v  = g_hp[(size_t)n * FO + t] / rs;
    v = v > 0.f ? v : expm1f(v);             // ELU (alpha=1)

    red[t] = v;
    __syncthreads();
#pragma unroll
    for (int s = 128; s; s >>= 1) {
        if (t < s) red[t] = fmaxf(red[t], red[t + s]);
        __syncthreads();
    }
    float mx = red[0];
    __syncthreads();

    red[t] = expf(v - mx);
    __syncthreads();
#pragma unroll
    for (int s = 128; s; s >>= 1) {
        if (t < s) red[t] += red[t + s];
        __syncthreads();
    }
    float lse = logf(red[0]) + mx;
    out[(size_t)n * FO + t] = v - lse;
}

// ======================= launch =======================
extern "C" void kernel_launch(void* const* d_in, const int* in_sizes, int n_in,
                              void* d_out, int out_size) {
    const float* x  = (const float*)d_in[0];
    const float* W  = (const float*)d_in[1];
    const float* a  = (const float*)d_in[2];
    const int*   ei = (const int*)d_in[3];
    const int*   row = ei;        // edge_index[0]
    const int*   col = ei + ER;   // edge_index[1]
    float* out = (float*)d_out;

    dim3 g1((NN + BM - 1) / BM, FO / BN);
    gemm_kernel   <<<g1, 256>>>(x, W);
    scores_kernel <<<(NN + 7) / 8, 256>>>(a);
    edge_kernel   <<<(ER + 255) / 256, 256>>>(row, col);
    scatter_kernel<<<ER / 4, 256>>>(row, col);      // 850000*64/256
    final_kernel  <<<NN, 256>>>(out);
}

// round 6
// speedup vs baseline: 1.0091x; 1.0091x over previous
// R6: R1's proven SIMT pipeline, with the atomic scatter replaced by an
// on-GPU CSR build + fused gather/normalize/ELU/log-softmax kernel.
// No mma.sync / ldmatrix / tcgen05 (both tensor paths are toolchain-dead).
#include <cuda_runtime.h>
#include <math.h>

#define NN 50000       // nodes
#define KD 512         // input feature dim
#define FO 256         // output classes
#define ER 850000      // edges: 800000 random + 50000 self loops

// -------- scratch (device globals; no allocation allowed) --------
__device__ __align__(16) float g_h[(size_t)NN * FO];   // h = x@W (51.2 MB, L2-resident)
__device__ float g_srow[NN];
__device__ float g_scol[NN];
__device__ int   g_cnt[NN];      // per-row degree
__device__ int   g_off[NN];      // CSR row start
__device__ int   g_cur[NN];      // fill cursor
__device__ int   g_ecol[ER];     // CSR: source node of each edge
__device__ float g_eval[ER];     // CSR: attention coefficient e

// ================= K1: SGEMM h = x @ W (R1-proven) =================
#define BM 128
#define BN 64
#define BK 16
#define TM 8
#define TN 4

__global__ __launch_bounds__(256) void gemm_kernel(const float* __restrict__ x,
                                                   const float* __restrict__ W) {
    __shared__ float As[BM][BK + 4];
    __shared__ float Bs[BK][BN];

    int tid = threadIdx.x;
    int tx = tid & 15;        // N direction (4 cols each)
    int ty = tid >> 4;        // M direction (8 rows each)
    int m0 = blockIdx.x * BM;
    int n0 = blockIdx.y * BN;

    float acc[TM][TN];
#pragma unroll
    for (int i = 0; i < TM; i++)
#pragma unroll
        for (int j = 0; j < TN; j++) acc[i][j] = 0.f;

    for (int k0 = 0; k0 < KD; k0 += BK) {
#pragma unroll
        for (int it = 0; it < 2; it++) {
            int f   = tid + it * 256;
            int row = f >> 2;
            int c4  = f & 3;
            int gr  = m0 + row;
            float4 v = make_float4(0.f, 0.f, 0.f, 0.f);
            if (gr < NN)
                v = *(const float4*)&x[(size_t)gr * KD + k0 + c4 * 4];
            *(float4*)&As[row][c4 * 4] = v;
        }
        {
            int row = tid >> 4;
            int c4  = tid & 15;
            *(float4*)&Bs[row][c4 * 4] =
                *(const float4*)&W[(size_t)(k0 + row) * FO + n0 + c4 * 4];
        }
        __syncthreads();

#pragma unroll
        for (int kk = 0; kk < BK; kk++) {
            float a_[TM];
#pragma unroll
            for (int i = 0; i < TM; i++) a_[i] = As[ty * TM + i][kk];
            float4 b4 = *(float4*)&Bs[kk][tx * TN];
            float b_[TN] = {b4.x, b4.y, b4.z, b4.w};
#pragma unroll
            for (int i = 0; i < TM; i++)
#pragma unroll
                for (int j = 0; j < TN; j++)
                    acc[i][j] = fmaf(a_[i], b_[j], acc[i][j]);
        }
        __syncthreads();
    }

#pragma unroll
    for (int i = 0; i < TM; i++) {
        int gr = m0 + ty * TM + i;
        if (gr < NN) {
            size_t off = (size_t)gr * FO + n0 + tx * TN;
            *(float4*)&g_h[off] = make_float4(acc[i][0], acc[i][1], acc[i][2], acc[i][3]);
        }
    }
}

// ========= K2: per-node scores + zero degree counters (R1-proven shape) =========
__global__ __launch_bounds__(256) void scores_kernel(const float* __restrict__ a) {
    int n    = blockIdx.x * (blockDim.x >> 5) + (threadIdx.x >> 5);
    int lane = threadIdx.x & 31;
    if (n >= NN) return;
    const float4* h4  = (const float4*)&g_h[(size_t)n * FO];
    const float4* a14 = (const float4*)a;          // a[0:256]
    const float4* a24 = (const float4*)(a + FO);   // a[256:512]
    float s1 = 0.f, s2 = 0.f;
#pragma unroll
    for (int it = 0; it < 2; it++) {
        int idx = lane + it * 32;
        float4 hv = h4[idx];
        float4 va = a14[idx];
        float4 vb = a24[idx];
        s1 += hv.x * va.x + hv.y * va.y + hv.z * va.z + hv.w * va.w;
        s2 += hv.x * vb.x + hv.y * vb.y + hv.z * vb.z + hv.w * vb.w;
    }
#pragma unroll
    for (int off = 16; off; off >>= 1) {
        s1 += __shfl_xor_sync(0xFFFFFFFFu, s1, off);
        s2 += __shfl_xor_sync(0xFFFFFFFFu, s2, off);
    }
    if (lane == 0) {
        g_srow[n] = s1;
        g_scol[n] = s2;
        g_cnt[n]  = 0;
    }
}

// ============ K3: degree histogram ============
__global__ __launch_bounds__(256) void hist_kernel(const int* __restrict__ row) {
    int i = blockIdx.x * blockDim.x + threadIdx.x;
    if (i >= ER) return;
    atomicAdd(&g_cnt[row[i]], 1);
}

// ============ K4: exclusive scan over 50000 degrees (single CTA) ============
#define SCAN_T 1024
#define SCAN_PER 49          // 1024 * 49 = 50176 >= NN
__global__ __launch_bounds__(SCAN_T) void scan_kernel() {
    __shared__ int sh[SCAN_T];
    int t = threadIdx.x;
    int base = t * SCAN_PER;
    int s = 0;
    for (int k = 0; k < SCAN_PER; k++) {
        int idx = base + k;
        if (idx < NN) s += g_cnt[idx];
    }
    sh[t] = s;
    __syncthreads();
    // Hillis-Steele inclusive scan
    for (int d = 1; d < SCAN_T; d <<= 1) {
        int v = (t >= d) ? sh[t - d] : 0;
        __syncthreads();
        sh[t] += v;
        __syncthreads();
    }
    int run = (t > 0) ? sh[t - 1] : 0;   // exclusive prefix of this thread's chunk
    for (int k = 0; k < SCAN_PER; k++) {
        int idx = base + k;
        if (idx < NN) {
            g_off[idx] = run;
            g_cur[idx] = run;
            run += g_cnt[idx];
        }
    }
}

// ============ K5: per-edge coefficient + CSR fill ============
__global__ __launch_bounds__(256) void edge_kernel(const int* __restrict__ row,
                                                   const int* __restrict__ col) {
    int i = blockIdx.x * blockDim.x + threadIdx.x;
    if (i >= ER) return;
    int r = row[i], c = col[i];
    float z = g_srow[r] + g_scol[c];
    float l = z > 0.f ? z : 0.2f * z;        // leaky_relu, slope 0.2
    float e = expf(-l);
    int pos = atomicAdd(&g_cur[r], 1);
    g_ecol[pos] = c;
    g_eval[pos] = e;
}

// ==== K6: fused gather-reduce + normalize + ELU + log_softmax ====
// One 256-thread block per node; thread t owns output feature t.
__global__ __launch_bounds__(256) void gather_final(float* __restrict__ out) {
    int n = blockIdx.x;
    int t = threadIdx.x;
    __shared__ float red[256];

    int start = g_off[n];
    int deg   = g_cnt[n];          // >= 1 (self loop)

    float acc = 0.f, rs = 0.f;
    int j = 0;
    for (; j + 2 <= deg; j += 2) {
        int   c0 = g_ecol[start + j];
        int   c1 = g_ecol[start + j + 1];
        float e0 = g_eval[start + j];
        float e1 = g_eval[start + j + 1];
        float h0 = g_h[(size_t)c0 * FO + t];
        float h1 = g_h[(size_t)c1 * FO + t];
        acc = fmaf(e0, h0, acc);
        acc = fmaf(e1, h1, acc);
        rs += e0 + e1;
    }
    if (j < deg) {
        int   c0 = g_ecol[start + j];
        float e0 = g_eval[start + j];
        acc = fmaf(e0, g_h[(size_t)c0 * FO + t], acc);
        rs += e0;
    }

    float v = acc / rs;
    v = v > 0.f ? v : expm1f(v);             // ELU (alpha=1)

    red[t] = v;
    __syncthreads();
#pragma unroll
    for (int s = 128; s; s >>= 1) {
        if (t < s) red[t] = fmaxf(red[t], red[t + s]);
        __syncthreads();
    }
    float mx = red[0];
    __syncthreads();

    red[t] = expf(v - mx);
    __syncthreads();
#pragma unroll
    for (int s = 128; s; s >>= 1) {
        if (t < s) red[t] += red[t + s];
        __syncthreads();
    }
    float lse = logf(red[0]) + mx;
    out[(size_t)n * FO + t] = v - lse;
}

// ======================= launch =======================
extern "C" void kernel_launch(void* const* d_in, const int* in_sizes, int n_in,
                              void* d_out, int out_size) {
    const float* x  = (const float*)d_in[0];
    const float* W  = (const float*)d_in[1];
    const float* a  = (const float*)d_in[2];
    const int*   ei = (const int*)d_in[3];
    const int*   row = ei;        // edge_index[0]
    const int*   col = ei + ER;   // edge_index[1]
    float* out = (float*)d_out;

    dim3 g1((NN + BM - 1) / BM, FO / BN);
    gemm_kernel  <<<g1, 256>>>(x, W);
    scores_kernel<<<(NN + 7) / 8, 256>>>(a);
    hist_kernel  <<<(ER + 255) / 256, 256>>>(row);
    scan_kernel  <<<1, SCAN_T>>>();
    edge_kernel  <<<(ER + 255) / 256, 256>>>(row, col);
    gather_final <<<NN, 256>>>(out);
}

// round 7
// speedup vs baseline: 1.1589x; 1.1485x over previous
// R7: R6 pipeline with (a) scan fixed (register-cached counters, kills the
// 80us serial global-reload chain) and (b) GEMM inner product converted to
// packed fma.rn.f32x2 (PTX sm_100+, legal at compute_103) for 2x FMA issue.
#include <cuda_runtime.h>
#include <math.h>
#include <stdint.h>

#define NN 50000       // nodes
#define KD 512         // input feature dim
#define FO 256         // output classes
#define ER 850000      // edges: 800000 random + 50000 self loops

// -------- scratch (device globals; no allocation allowed) --------
__device__ __align__(16) float g_h[(size_t)NN * FO];   // h = x@W (51.2 MB)
__device__ float g_srow[NN];
__device__ float g_scol[NN];
__device__ int   g_cnt[NN];      // per-row degree
__device__ int   g_off[NN];      // CSR row start
__device__ int   g_cur[NN];      // fill cursor
__device__ int   g_ecol[ER];     // CSR: source node of each edge
__device__ float g_eval[ER];     // CSR: attention coefficient e

// ---- packed f32x2 helpers ----
__device__ __forceinline__ uint64_t pack2(float lo, float hi) {
    uint64_t p;
    asm("mov.b64 %0, {%1, %2};" : "=l"(p) : "f"(lo), "f"(hi));
    return p;
}
__device__ __forceinline__ void unpack2(uint64_t p, float &lo, float &hi) {
    asm("mov.b64 {%0, %1}, %2;" : "=f"(lo), "=f"(hi) : "l"(p));
}
__device__ __forceinline__ void fma2(uint64_t &d, uint64_t a, uint64_t b) {
    asm("fma.rn.f32x2 %0, %1, %2, %0;" : "+l"(d) : "l"(a), "l"(b));
}

// ================= K1: SGEMM h = x @ W via fma.rn.f32x2 =================
// CTA 128x64, BK=16, 256 threads, thread tile 8(M) x 4(N).
// Accumulators are M-adjacent pairs packed in 64-bit regs (4 pairs x 4 n).
#define BM 128
#define BN 64
#define BK 16
#define TM 8
#define TN 4
#define AK_STRIDE 130   // floats per k-row of As (130%32=2 -> STS banks spread; even -> 8B aligned)

__global__ __launch_bounds__(256) void gemm_kernel(const float* __restrict__ x,
                                                   const float* __restrict__ W) {
    __shared__ float Ask[BK * AK_STRIDE];   // k-major: Ask[k][m]
    __shared__ float Bs[BK][BN];

    int tid = threadIdx.x;
    int tx = tid & 15;        // N direction (4 cols each)
    int ty = tid >> 4;        // M direction (8 rows each)
    int m0 = blockIdx.x * BM;
    int n0 = blockIdx.y * BN;

    uint64_t acc[TM / 2][TN];       // pair (m, m+1) x n
#pragma unroll
    for (int i = 0; i < TM / 2; i++)
#pragma unroll
        for (int j = 0; j < TN; j++) acc[i][j] = pack2(0.f, 0.f);

    for (int k0 = 0; k0 < KD; k0 += BK) {
        // ---- load A tile 128x16, store k-major ----
#pragma unroll
        for (int it = 0; it < 2; it++) {
            int f   = tid + it * 256;
            int row = f >> 2;       // 0..127 (m)
            int c4  = f & 3;        // k group
            int gr  = m0 + row;
            float4 v = make_float4(0.f, 0.f, 0.f, 0.f);
            if (gr < NN)
                v = *(const float4*)&x[(size_t)gr * KD + k0 + c4 * 4];
            Ask[(c4 * 4 + 0) * AK_STRIDE + row] = v.x;
            Ask[(c4 * 4 + 1) * AK_STRIDE + row] = v.y;
            Ask[(c4 * 4 + 2) * AK_STRIDE + row] = v.z;
            Ask[(c4 * 4 + 3) * AK_STRIDE + row] = v.w;
        }
        // ---- load B tile 16x64 ----
        {
            int row = tid >> 4;     // k
            int c4  = tid & 15;
            *(float4*)&Bs[row][c4 * 4] =
                *(const float4*)&W[(size_t)(k0 + row) * FO + n0 + c4 * 4];
        }
        __syncthreads();

#pragma unroll
        for (int kk = 0; kk < BK; kk++) {
            // a pairs: LDS.64 each (m even, 8B aligned)
            uint64_t ap[TM / 2];
#pragma unroll
            for (int i = 0; i < TM / 2; i++)
                ap[i] = *(const uint64_t*)&Ask[kk * AK_STRIDE + ty * TM + 2 * i];
            float4 b4 = *(float4*)&Bs[kk][tx * TN];
            uint64_t bd[TN] = { pack2(b4.x, b4.x), pack2(b4.y, b4.y),
                                pack2(b4.z, b4.z), pack2(b4.w, b4.w) };
#pragma unroll
            for (int i = 0; i < TM / 2; i++)
#pragma unroll
                for (int j = 0; j < TN; j++)
                    fma2(acc[i][j], ap[i], bd[j]);
        }
        __syncthreads();
    }

    // ---- epilogue ----
#pragma unroll
    for (int i = 0; i < TM / 2; i++) {
        float lo[TN], hi[TN];
#pragma unroll
        for (int j = 0; j < TN; j++) unpack2(acc[i][j], lo[j], hi[j]);
        int gr0 = m0 + ty * TM + 2 * i;
        if (gr0 < NN)
            *(float4*)&g_h[(size_t)gr0 * FO + n0 + tx * TN] =
                make_float4(lo[0], lo[1], lo[2], lo[3]);
        if (gr0 + 1 < NN)
            *(float4*)&g_h[(size_t)(gr0 + 1) * FO + n0 + tx * TN] =
                make_float4(hi[0], hi[1], hi[2], hi[3]);
    }
}

// ========= K2: per-node scores + zero degree counters =========
__global__ __launch_bounds__(256) void scores_kernel(const float* __restrict__ a) {
    int n    = blockIdx.x * (blockDim.x >> 5) + (threadIdx.x >> 5);
    int lane = threadIdx.x & 31;
    if (n >= NN) return;
    const float4* h4  = (const float4*)&g_h[(size_t)n * FO];
    const float4* a14 = (const float4*)a;          // a[0:256]
    const float4* a24 = (const float4*)(a + FO);   // a[256:512]
    float s1 = 0.f, s2 = 0.f;
#pragma unroll
    for (int it = 0; it < 2; it++) {
        int idx = lane + it * 32;
        float4 hv = h4[idx];
        float4 va = a14[idx];
        float4 vb = a24[idx];
        s1 += hv.x * va.x + hv.y * va.y + hv.z * va.z + hv.w * va.w;
        s2 += hv.x * vb.x + hv.y * vb.y + hv.z * vb.z + hv.w * vb.w;
    }
#pragma unroll
    for (int off = 16; off; off >>= 1) {
        s1 += __shfl_xor_sync(0xFFFFFFFFu, s1, off);
        s2 += __shfl_xor_sync(0xFFFFFFFFu, s2, off);
    }
    if (lane == 0) {
        g_srow[n] = s1;
        g_scol[n] = s2;
        g_cnt[n]  = 0;
    }
}

// ============ K3: degree histogram ============
__global__ __launch_bounds__(256) void hist_kernel(const int* __restrict__ row) {
    int i = blockIdx.x * blockDim.x + threadIdx.x;
    if (i >= ER) return;
    atomicAdd(&g_cnt[row[i]], 1);
}

// ============ K4: exclusive scan over 50000 degrees (single CTA) ============
// Counter values are cached in a per-thread local array between the two
// passes (the R6 version re-read g_cnt from global in a serial chain: 80us).
#define SCAN_T 1024
#define SCAN_PER 49          // 1024 * 49 = 50176 >= NN
__global__ __launch_bounds__(SCAN_T) void scan_kernel() {
    __shared__ int sh[SCAN_T];
    int t = threadIdx.x;
    int base = t * SCAN_PER;
    int cloc[SCAN_PER];
    int s = 0;
#pragma unroll
    for (int k = 0; k < SCAN_PER; k++) {
        int idx = base + k;
        cloc[k] = (idx < NN) ? g_cnt[idx] : 0;
        s += cloc[k];
    }
    sh[t] = s;
    __syncthreads();
    for (int d = 1; d < SCAN_T; d <<= 1) {
        int v = (t >= d) ? sh[t - d] : 0;
        __syncthreads();
        sh[t] += v;
        __syncthreads();
    }
    int run = (t > 0) ? sh[t - 1] : 0;
#pragma unroll
    for (int k = 0; k < SCAN_PER; k++) {
        int idx = base + k;
        if (idx < NN) {
            g_off[idx] = run;
            g_cur[idx] = run;
            run += cloc[k];
        }
    }
}

// ============ K5: per-edge coefficient + CSR fill ============
__global__ __launch_bounds__(256) void edge_kernel(const int* __restrict__ row,
                                                   const int* __restrict__ col) {
    int i = blockIdx.x * blockDim.x + threadIdx.x;
    if (i >= ER) return;
    int r = row[i], c = col[i];
    float z = g_srow[r] + g_scol[c];
    float l = z > 0.f ? z : 0.2f * z;        // leaky_relu, slope 0.2
    float e = expf(-l);
    int pos = atomicAdd(&g_cur[r], 1);
    g_ecol[pos] = c;
    g_eval[pos] = e;
}

// ==== K6: fused gather-reduce + normalize + ELU + log_softmax ====
__global__ __launch_bounds__(256) void gather_final(float* __restrict__ out) {
    int n = blockIdx.x;
    int t = threadIdx.x;
    __shared__ float red[256];

    int start = g_off[n];
    int deg   = g_cnt[n];          // >= 1 (self loop)

    float a0 = 0.f, a1 = 0.f, rs = 0.f;
    int j = 0;
    for (; j + 4 <= deg; j += 4) {
        int   c0 = g_ecol[start + j];
        int   c1 = g_ecol[start + j + 1];
        int   c2 = g_ecol[start + j + 2];
        int   c3 = g_ecol[start + j + 3];
        float e0 = g_eval[start + j];
        float e1 = g_eval[start + j + 1];
        float e2 = g_eval[start + j + 2];
        float e3 = g_eval[start + j + 3];
        float h0 = g_h[(size_t)c0 * FO + t];
        float h1 = g_h[(size_t)c1 * FO + t];
        float h2 = g_h[(size_t)c2 * FO + t];
        float h3 = g_h[(size_t)c3 * FO + t];
        a0 = fmaf(e0, h0, a0);
        a1 = fmaf(e1, h1, a1);
        a0 = fmaf(e2, h2, a0);
        a1 = fmaf(e3, h3, a1);
        rs += (e0 + e1) + (e2 + e3);
    }
    for (; j < deg; j++) {
        int   c0 = g_ecol[start + j];
        float e0 = g_eval[start + j];
        a0 = fmaf(e0, g_h[(size_t)c0 * FO + t], a0);
        rs += e0;
    }

    float v = (a0 + a1) / rs;
    v = v > 0.f ? v : expm1f(v);             // ELU (alpha=1)

    red[t] = v;
    __syncthreads();
#pragma unroll
    for (int s = 128; s; s >>= 1) {
        if (t < s) red[t] = fmaxf(red[t], red[t + s]);
        __syncthreads();
    }
    float mx = red[0];
    __syncthreads();

    red[t] = expf(v - mx);
    __syncthreads();
#pragma unroll
    for (int s = 128; s; s >>= 1) {
        if (t < s) red[t] += red[t + s];
        __syncthreads();
    }
    float lse = logf(red[0]) + mx;
    out[(size_t)n * FO + t] = v - lse;
}

// ======================= launch =======================
extern "C" void kernel_launch(void* const* d_in, const int* in_sizes, int n_in,
                              void* d_out, int out_size) {
    const float* x  = (const float*)d_in[0];
    const float* W  = (const float*)d_in[1];
    const float* a  = (const float*)d_in[2];
    const int*   ei = (const int*)d_in[3];
    const int*   row = ei;        // edge_index[0]
    const int*   col = ei + ER;   // edge_index[1]
    float* out = (float*)d_out;

    dim3 g1((NN + BM - 1) / BM, FO / BN);
    gemm_kernel  <<<g1, 256>>>(x, W);
    scores_kernel<<<(NN + 7) / 8, 256>>>(a);
    hist_kernel  <<<(ER + 255) / 256, 256>>>(row);
    scan_kernel  <<<1, SCAN_T>>>();
    edge_kernel  <<<(ER + 255) / 256, 256>>>(row, col);
    gather_final <<<NN, 256>>>(out);
}

// round 8
// speedup vs baseline: 1.2309x; 1.0621x over previous
// R8: (a) 3-pass multi-block scan (R7's single-CTA scan spilled and ran a
// 61us latency chain), (b) GEMM grid swapped so x streams DRAM once, and
// (c) GEMM smem double-buffered (one barrier per chunk, load/compute overlap).
#include <cuda_runtime.h>
#include <math.h>
#include <stdint.h>

#define NN 50000       // nodes
#define KD 512         // input feature dim
#define FO 256         // output classes
#define ER 850000      // edges: 800000 random + 50000 self loops

// -------- scratch (device globals; no allocation allowed) --------
__device__ __align__(16) float g_h[(size_t)NN * FO];   // h = x@W (51.2 MB)
__device__ float g_srow[NN];
__device__ float g_scol[NN];
__device__ int   g_cnt[NN];      // per-row degree
__device__ int   g_off[NN];      // CSR row start
__device__ int   g_cur[NN];      // fill cursor
__device__ int   g_ecol[ER];     // CSR: source node of each edge
__device__ float g_eval[ER];     // CSR: attention coefficient e
#define SCAN_B 196               // scan blocks (196*256 = 50176 >= NN)
__device__ int   g_part[SCAN_B]; // per-block partial sums

// ---- packed f32x2 helpers ----
__device__ __forceinline__ uint64_t pack2(float lo, float hi) {
    uint64_t p;
    asm("mov.b64 %0, {%1, %2};" : "=l"(p) : "f"(lo), "f"(hi));
    return p;
}
__device__ __forceinline__ void unpack2(uint64_t p, float &lo, float &hi) {
    asm("mov.b64 {%0, %1}, %2;" : "=f"(lo), "=f"(hi) : "l"(p));
}
__device__ __forceinline__ void fma2(uint64_t &d, uint64_t a, uint64_t b) {
    asm("fma.rn.f32x2 %0, %1, %2, %0;" : "+l"(d) : "l"(a), "l"(b));
}

// ================= K1: SGEMM h = x @ W via fma.rn.f32x2, double-buffered =================
#define BM 128
#define BN 64
#define BK 16
#define TM 8
#define TN 4
#define AK_STRIDE 130   // floats per k-row of As (even -> 8B aligned; %32=2 -> banks spread)
#define NCHUNK (KD / BK)

__global__ __launch_bounds__(256) void gemm_kernel(const float* __restrict__ x,
                                                   const float* __restrict__ W) {
    __shared__ float Ask[2][BK * AK_STRIDE];   // k-major: Ask[buf][k][m]
    __shared__ float Bs[2][BK][BN];

    int tid = threadIdx.x;
    int tx = tid & 15;        // N direction (4 cols each)
    int ty = tid >> 4;        // M direction (8 rows each)
    int n0 = blockIdx.x * BN;     // x-dim = N (4 tiles) -> adjacent CTAs share x slab
    int m0 = blockIdx.y * BM;

    // gmem load roles
    const int arow = tid >> 1;             // 0..127 (two threads per row)
    const int ak4  = (tid & 1) * 2;        // k-group 0..1 / 2..3
    const bool aok = (m0 + arow) < NN;
    const int brow = tid >> 4;             // 0..15 (k)
    const int bc4  = tid & 15;

    uint64_t acc[TM / 2][TN];
#pragma unroll
    for (int i = 0; i < TM / 2; i++)
#pragma unroll
        for (int j = 0; j < TN; j++) acc[i][j] = pack2(0.f, 0.f);

    // prologue: load chunk 0 into buffer 0
    {
        const float* srcA = x + (size_t)(m0 + arow) * KD + ak4 * 4;
#pragma unroll
        for (int g = 0; g < 2; g++) {
            float4 v = aok ? *(const float4*)(srcA + g * 4)
                           : make_float4(0.f, 0.f, 0.f, 0.f);
            int kb = (ak4 + g) * 4;
            Ask[0][(kb + 0) * AK_STRIDE + arow] = v.x;
            Ask[0][(kb + 1) * AK_STRIDE + arow] = v.y;
            Ask[0][(kb + 2) * AK_STRIDE + arow] = v.z;
            Ask[0][(kb + 3) * AK_STRIDE + arow] = v.w;
        }
        *(float4*)&Bs[0][brow][bc4 * 4] =
            *(const float4*)&W[(size_t)brow * FO + n0 + bc4 * 4];
    }
    __syncthreads();

    for (int c = 0; c < NCHUNK; c++) {
        int buf = c & 1;
        // ---- prefetch chunk c+1 into the other buffer ----
        if (c + 1 < NCHUNK) {
            int nxt = buf ^ 1;
            int k0 = (c + 1) * BK;
            const float* srcA = x + (size_t)(m0 + arow) * KD + k0 + ak4 * 4;
#pragma unroll
            for (int g = 0; g < 2; g++) {
                float4 v = aok ? *(const float4*)(srcA + g * 4)
                               : make_float4(0.f, 0.f, 0.f, 0.f);
                int kb = (ak4 + g) * 4;
                Ask[nxt][(kb + 0) * AK_STRIDE + arow] = v.x;
                Ask[nxt][(kb + 1) * AK_STRIDE + arow] = v.y;
                Ask[nxt][(kb + 2) * AK_STRIDE + arow] = v.z;
                Ask[nxt][(kb + 3) * AK_STRIDE + arow] = v.w;
            }
            *(float4*)&Bs[nxt][brow][bc4 * 4] =
                *(const float4*)&W[(size_t)(k0 + brow) * FO + n0 + bc4 * 4];
        }
        // ---- compute on current buffer ----
#pragma unroll
        for (int kk = 0; kk < BK; kk++) {
            uint64_t ap[TM / 2];
#pragma unroll
            for (int i = 0; i < TM / 2; i++)
                ap[i] = *(const uint64_t*)&Ask[buf][kk * AK_STRIDE + ty * TM + 2 * i];
            float4 b4 = *(float4*)&Bs[buf][kk][tx * TN];
            uint64_t bd[TN] = { pack2(b4.x, b4.x), pack2(b4.y, b4.y),
                                pack2(b4.z, b4.z), pack2(b4.w, b4.w) };
#pragma unroll
            for (int i = 0; i < TM / 2; i++)
#pragma unroll
                for (int j = 0; j < TN; j++)
                    fma2(acc[i][j], ap[i], bd[j]);
        }
        __syncthreads();
    }

    // ---- epilogue ----
#pragma unroll
    for (int i = 0; i < TM / 2; i++) {
        float lo[TN], hi[TN];
#pragma unroll
        for (int j = 0; j < TN; j++) unpack2(acc[i][j], lo[j], hi[j]);
        int gr0 = m0 + ty * TM + 2 * i;
        if (gr0 < NN)
            *(float4*)&g_h[(size_t)gr0 * FO + n0 + tx * TN] =
                make_float4(lo[0], lo[1], lo[2], lo[3]);
        if (gr0 + 1 < NN)
            *(float4*)&g_h[(size_t)(gr0 + 1) * FO + n0 + tx * TN] =
                make_float4(hi[0], hi[1], hi[2], hi[3]);
    }
}

// ========= K2: per-node scores + zero degree counters =========
__global__ __launch_bounds__(256) void scores_kernel(const float* __restrict__ a) {
    int n    = blockIdx.x * (blockDim.x >> 5) + (threadIdx.x >> 5);
    int lane = threadIdx.x & 31;
    if (n >= NN) return;
    const float4* h4  = (const float4*)&g_h[(size_t)n * FO];
    const float4* a14 = (const float4*)a;          // a[0:256]
    const float4* a24 = (const float4*)(a + FO);   // a[256:512]
    float s1 = 0.f, s2 = 0.f;
#pragma unroll
    for (int it = 0; it < 2; it++) {
        int idx = lane + it * 32;
        float4 hv = h4[idx];
        float4 va = a14[idx];
        float4 vb = a24[idx];
        s1 += hv.x * va.x + hv.y * va.y + hv.z * va.z + hv.w * va.w;
        s2 += hv.x * vb.x + hv.y * vb.y + hv.z * vb.z + hv.w * vb.w;
    }
#pragma unroll
    for (int off = 16; off; off >>= 1) {
        s1 += __shfl_xor_sync(0xFFFFFFFFu, s1, off);
        s2 += __shfl_xor_sync(0xFFFFFFFFu, s2, off);
    }
    if (lane == 0) {
        g_srow[n] = s1;
        g_scol[n] = s2;
        g_cnt[n]  = 0;
    }
}

// ============ K3: degree histogram ============
__global__ __launch_bounds__(256) void hist_kernel(const int* __restrict__ row) {
    int i = blockIdx.x * blockDim.x + threadIdx.x;
    if (i >= ER) return;
    atomicAdd(&g_cnt[row[i]], 1);
}

// ============ K4a/b/c: 3-pass parallel exclusive scan over g_cnt ============
__global__ __launch_bounds__(256) void scan_reduce() {
    __shared__ int sh[256];
    int t = threadIdx.x;
    int idx = blockIdx.x * 256 + t;
    int v = (idx < NN) ? g_cnt[idx] : 0;
    sh[t] = v;
    __syncthreads();
#pragma unroll
    for (int s = 128; s; s >>= 1) {
        if (t < s) sh[t] += sh[t + s];
        __syncthreads();
    }
    if (t == 0) g_part[blockIdx.x] = sh[0];
}

__global__ __launch_bounds__(256) void scan_partials() {
    __shared__ int sh[256];
    int t = threadIdx.x;
    sh[t] = (t < SCAN_B) ? g_part[t] : 0;
    __syncthreads();
    // Hillis-Steele inclusive scan over 256
#pragma unroll
    for (int d = 1; d < 256; d <<= 1) {
        int v = (t >= d) ? sh[t - d] : 0;
        __syncthreads();
        sh[t] += v;
        __syncthreads();
    }
    if (t < SCAN_B) g_part[t] = (t > 0) ? sh[t - 1] : 0;   // exclusive
}

__global__ __launch_bounds__(256) void scan_write() {
    __shared__ int sh[256];
    int t = threadIdx.x;
    int idx = blockIdx.x * 256 + t;
    int v = (idx < NN) ? g_cnt[idx] : 0;
    sh[t] = v;
    __syncthreads();
#pragma unroll
    for (int d = 1; d < 256; d <<= 1) {
        int u = (t >= d) ? sh[t - d] : 0;
        __syncthreads();
        sh[t] += u;
        __syncthreads();
    }
    if (idx < NN) {
        int off = g_part[blockIdx.x] + sh[t] - v;   // exclusive = inclusive - self
        g_off[idx] = off;
        g_cur[idx] = off;
    }
}

// ============ K5: per-edge coefficient + CSR fill ============
__global__ __launch_bounds__(256) void edge_kernel(const int* __restrict__ row,
                                                   const int* __restrict__ col) {
    int i = blockIdx.x * blockDim.x + threadIdx.x;
    if (i >= ER) return;
    int r = row[i], c = col[i];
    float z = g_srow[r] + g_scol[c];
    float l = z > 0.f ? z : 0.2f * z;        // leaky_relu, slope 0.2
    float e = expf(-l);
    int pos = atomicAdd(&g_cur[r], 1);
    g_ecol[pos] = c;
    g_eval[pos] = e;
}

// ==== K6: fused gather-reduce + normalize + ELU + log_softmax ====
__global__ __launch_bounds__(256) void gather_final(float* __restrict__ out) {
    int n = blockIdx.x;
    int t = threadIdx.x;
    __shared__ float red[256];

    int start = g_off[n];
    int deg   = g_cnt[n];          // >= 1 (self loop)

    float a0 = 0.f, a1 = 0.f, rs = 0.f;
    int j = 0;
    for (; j + 4 <= deg; j += 4) {
        int   c0 = g_ecol[start + j];
        int   c1 = g_ecol[start + j + 1];
        int   c2 = g_ecol[start + j + 2];
        int   c3 = g_ecol[start + j + 3];
        float e0 = g_eval[start + j];
        float e1 = g_eval[start + j + 1];
        float e2 = g_eval[start + j + 2];
        float e3 = g_eval[start + j + 3];
        float h0 = g_h[(size_t)c0 * FO + t];
        float h1 = g_h[(size_t)c1 * FO + t];
        float h2 = g_h[(size_t)c2 * FO + t];
        float h3 = g_h[(size_t)c3 * FO + t];
        a0 = fmaf(e0, h0, a0);
        a1 = fmaf(e1, h1, a1);
        a0 = fmaf(e2, h2, a0);
        a1 = fmaf(e3, h3, a1);
        rs += (e0 + e1) + (e2 + e3);
    }
    for (; j < deg; j++) {
        int   c0 = g_ecol[start + j];
        float e0 = g_eval[start + j];
        a0 = fmaf(e0, g_h[(size_t)c0 * FO + t], a0);
        rs += e0;
    }

    float v = (a0 + a1) / rs;
    v = v > 0.f ? v : expm1f(v);             // ELU (alpha=1)

    red[t] = v;
    __syncthreads();
#pragma unroll
    for (int s = 128; s; s >>= 1) {
        if (t < s) red[t] = fmaxf(red[t], red[t + s]);
        __syncthreads();
    }
    float mx = red[0];
    __syncthreads();

    red[t] = expf(v - mx);
    __syncthreads();
#pragma unroll
    for (int s = 128; s; s >>= 1) {
        if (t < s) red[t] += red[t + s];
        __syncthreads();
    }
    float lse = logf(red[0]) + mx;
    out[(size_t)n * FO + t] = v - lse;
}

// ======================= launch =======================
extern "C" void kernel_launch(void* const* d_in, const int* in_sizes, int n_in,
                              void* d_out, int out_size) {
    const float* x  = (const float*)d_in[0];
    const float* W  = (const float*)d_in[1];
    const float* a  = (const float*)d_in[2];
    const int*   ei = (const int*)d_in[3];
    const int*   row = ei;        // edge_index[0]
    const int*   col = ei + ER;   // edge_index[1]
    float* out = (float*)d_out;

    dim3 g1(FO / BN, (NN + BM - 1) / BM);    // N fastest -> x slab reused in L2
    gemm_kernel  <<<g1, 256>>>(x, W);
    scores_kernel<<<(NN + 7) / 8, 256>>>(a);
    hist_kernel  <<<(ER + 255) / 256, 256>>>(row);
    scan_reduce  <<<SCAN_B, 256>>>();
    scan_partials<<<1, 256>>>();
    scan_write   <<<SCAN_B, 256>>>();
    edge_kernel  <<<(ER + 255) / 256, 256>>>(row, col);
    gather_final <<<NN, 256>>>(out);
}